// round 16
// baseline (speedup 1.0000x reference)
#include <cuda_runtime.h>
#include <cuda_bf16.h>
#include <cstddef>
#include <cstdint>

// FM layer:
//   idx[b,j] = N_DENSE + j*PER_FIELD + sparse[b,j]
//   first[b] = w0 + dense[b,:]·w[:13] + sum_j w[idx[b,j]]
//   e_k[b]   = dense[b,:]·V[k,:13] + sum_j V[k, idx[b,j]]
//   sq_k[b]  = (dense[b,:]^2)·(V[k,:13]^2) + sum_j V[k, idx[b,j]]^2
//   out[b]   = first[b] + 0.5 * sum_k (e_k^2 - sq_k)
//
// Inputs (metadata order):
//   d_in[0] dense  f32 [4096,13]   d_in[1] sparse i32 [4096,26]
//   d_in[2] w0     f32 [1]         d_in[3] w      f32 [2600013,1]
//   d_in[4] V      f32 [16,2600013]
// Output: f32 [4096,1]
//
// Strategy: thread = (b, k). All 26 scattered V gathers are issued as 4-byte
// cp.async (LDGSTS) — no destination registers, so full MLP=26 per thread at
// ~40 live regs, letting 32 warps/SM keep ~800+ warp-loads outstanding and
// pin the DRAM pipe. First-order (w) and dense work execute inside the
// cp.async latency shadow. Each thread reads back only its own smem slots.

#define FM_BATCH     4096
#define FM_NDENSE    13
#define FM_NFIELDS   26
#define FM_PERFIELD  100000
#define FM_FEATNUM   2600013
#define FM_K         16

#define CTA_THREADS  128
#define GSTRIDE      27          // pad 26 -> 27 (gcd(27,32)=1, conflict-free LDS)

__device__ __forceinline__ void cp_async_4B(uint32_t smem_addr, const float* gptr) {
    asm volatile("cp.async.ca.shared.global [%0], [%1], 4;"
                 :: "r"(smem_addr), "l"(gptr));
}

__global__ __launch_bounds__(CTA_THREADS, 8)
void fm_layer_kernel(const float* __restrict__ dense,
                     const int*   __restrict__ sparse,
                     const float* __restrict__ w0,
                     const float* __restrict__ w,
                     const float* __restrict__ V,
                     float*       __restrict__ out)
{
    __shared__ float gbuf[CTA_THREADS * GSTRIDE];

    const int t  = threadIdx.x;
    const int gt = blockIdx.x * CTA_THREADS + t;
    const int b  = gt >> 4;        // batch row
    const int k  = gt & 15;        // latent dim handled by this lane

    const int*   sp = sparse + b * FM_NFIELDS;
    const float* db = dense  + b * FM_NDENSE;
    const float* Vk = V + (size_t)k * FM_FEATNUM;

    const uint32_t sbase =
        (uint32_t)__cvta_generic_to_shared(&gbuf[t * GSTRIDE]);

    // ---- issue all 26 scattered V gathers as register-free cp.async ----
#pragma unroll
    for (int j = 0; j < FM_NFIELDS; j++) {
        const int idx = FM_NDENSE + j * FM_PERFIELD + __ldg(sp + j);
        cp_async_4B(sbase + j * 4, Vk + idx);
    }
    asm volatile("cp.async.commit_group;");

    // ---- work inside the gather latency shadow ----
    // first order, spread over the 16 lanes: sparse fields k and k+16
    float fo = __ldg(w + FM_NDENSE + k * FM_PERFIELD + __ldg(sp + k));
    if (k + 16 < FM_NFIELDS) {
        const int j2 = k + 16;
        fo += __ldg(w + FM_NDENSE + j2 * FM_PERFIELD + __ldg(sp + j2));
    }
    if (k < FM_NDENSE)
        fo = fmaf(__ldg(db + k), __ldg(w + k), fo);

    // dense contribution to e_k / sq_k (V[k,0:13] hot in cache)
    float e = 0.0f, s = 0.0f;
#pragma unroll
    for (int d = 0; d < FM_NDENSE; d++) {
        const float x  = __ldg(db + d);
        const float v  = __ldg(Vk + d);
        e = fmaf(x, v, e);
        const float xv = x * v;
        s = fmaf(xv, xv, s);
    }

    // ---- drain gathers (own-thread smem slots: no block sync needed) ----
    asm volatile("cp.async.wait_group 0;");

    const float* my = &gbuf[t * GSTRIDE];
#pragma unroll
    for (int j = 0; j < FM_NFIELDS; j++) {
        const float g = my[j];
        e += g;
        s  = fmaf(g, g, s);
    }

    float tot = fmaf(0.5f, e * e - s, fo);   // 0.5*(e^2 - sq) + first-order part

    // ---- reduce over the 16 lanes of this row (xor < 16 stays in group) ----
#pragma unroll
    for (int m = 8; m >= 1; m >>= 1)
        tot += __shfl_xor_sync(0xFFFFFFFFu, tot, m);

    if (k == 0)
        out[b] = tot + __ldg(w0);
}

extern "C" void kernel_launch(void* const* d_in, const int* in_sizes, int n_in,
                              void* d_out, int out_size)
{
    const float* dense  = (const float*)d_in[0];
    const int*   sparse = (const int*)  d_in[1];
    const float* w0     = (const float*)d_in[2];
    const float* w      = (const float*)d_in[3];
    const float* V      = (const float*)d_in[4];
    float*       out    = (float*)d_out;

    const int total  = FM_BATCH * FM_K;            // 65536 threads
    const int blocks = total / CTA_THREADS;        // 512 CTAs
    fm_layer_kernel<<<blocks, CTA_THREADS>>>(dense, sparse, w0, w, V, out);
}

// round 17
// speedup vs baseline: 1.0502x; 1.0502x over previous
#include <cuda_runtime.h>
#include <cuda_bf16.h>
#include <cstddef>
#include <cstdint>

// FM layer:
//   idx[b,j] = N_DENSE + j*PER_FIELD + sparse[b,j]
//   first[b] = w0 + dense[b,:]·w[:13] + sum_j w[idx[b,j]]
//   e_k[b]   = dense[b,:]·V[k,:13] + sum_j V[k, idx[b,j]]
//   sq_k[b]  = (dense[b,:]^2)·(V[k,:13]^2) + sum_j V[k, idx[b,j]]^2
//   out[b]   = first[b] + 0.5 * sum_k (e_k^2 - sq_k)
//
// Inputs (metadata order):
//   d_in[0] dense  f32 [4096,13]   d_in[1] sparse i32 [4096,26]
//   d_in[2] w0     f32 [1]         d_in[3] w      f32 [2600013,1]
//   d_in[4] V      f32 [16,2600013]
// Output: f32 [4096,1]
//
// Strategy: thread = (b, k). All 26 scattered V gathers are issued as 4-byte
// cp.async (LDGSTS) — no destination registers, so full MLP=26 per thread at
// ~40 live regs, letting 32 warps/SM keep ~800+ warp-loads outstanding and
// pin the DRAM pipe. First-order (w) and dense work execute inside the
// cp.async latency shadow. Each thread reads back only its own smem slots.

#define FM_BATCH     4096
#define FM_NDENSE    13
#define FM_NFIELDS   26
#define FM_PERFIELD  100000
#define FM_FEATNUM   2600013
#define FM_K         16

#define CTA_THREADS  128
#define GSTRIDE      27          // pad 26 -> 27 (gcd(27,32)=1, conflict-free LDS)

__device__ __forceinline__ void cp_async_4B(uint32_t smem_addr, const float* gptr) {
    asm volatile("cp.async.ca.shared.global [%0], [%1], 4;"
                 :: "r"(smem_addr), "l"(gptr));
}

__global__ __launch_bounds__(CTA_THREADS, 8)
void fm_layer_kernel(const float* __restrict__ dense,
                     const int*   __restrict__ sparse,
                     const float* __restrict__ w0,
                     const float* __restrict__ w,
                     const float* __restrict__ V,
                     float*       __restrict__ out)
{
    __shared__ float gbuf[CTA_THREADS * GSTRIDE];

    const int t  = threadIdx.x;
    const int gt = blockIdx.x * CTA_THREADS + t;
    const int b  = gt >> 4;        // batch row
    const int k  = gt & 15;        // latent dim handled by this lane

    const int*   sp = sparse + b * FM_NFIELDS;
    const float* db = dense  + b * FM_NDENSE;
    const float* Vk = V + (size_t)k * FM_FEATNUM;

    const uint32_t sbase =
        (uint32_t)__cvta_generic_to_shared(&gbuf[t * GSTRIDE]);

    // ---- issue all 26 scattered V gathers as register-free cp.async ----
#pragma unroll
    for (int j = 0; j < FM_NFIELDS; j++) {
        const int idx = FM_NDENSE + j * FM_PERFIELD + __ldg(sp + j);
        cp_async_4B(sbase + j * 4, Vk + idx);
    }
    asm volatile("cp.async.commit_group;");

    // ---- work inside the gather latency shadow ----
    // first order, spread over the 16 lanes: sparse fields k and k+16
    float fo = __ldg(w + FM_NDENSE + k * FM_PERFIELD + __ldg(sp + k));
    if (k + 16 < FM_NFIELDS) {
        const int j2 = k + 16;
        fo += __ldg(w + FM_NDENSE + j2 * FM_PERFIELD + __ldg(sp + j2));
    }
    if (k < FM_NDENSE)
        fo = fmaf(__ldg(db + k), __ldg(w + k), fo);

    // dense contribution to e_k / sq_k (V[k,0:13] hot in cache)
    float e = 0.0f, s = 0.0f;
#pragma unroll
    for (int d = 0; d < FM_NDENSE; d++) {
        const float x  = __ldg(db + d);
        const float v  = __ldg(Vk + d);
        e = fmaf(x, v, e);
        const float xv = x * v;
        s = fmaf(xv, xv, s);
    }

    // ---- drain gathers (own-thread smem slots: no block sync needed) ----
    asm volatile("cp.async.wait_group 0;");

    const float* my = &gbuf[t * GSTRIDE];
#pragma unroll
    for (int j = 0; j < FM_NFIELDS; j++) {
        const float g = my[j];
        e += g;
        s  = fmaf(g, g, s);
    }

    float tot = fmaf(0.5f, e * e - s, fo);   // 0.5*(e^2 - sq) + first-order part

    // ---- reduce over the 16 lanes of this row (xor < 16 stays in group) ----
#pragma unroll
    for (int m = 8; m >= 1; m >>= 1)
        tot += __shfl_xor_sync(0xFFFFFFFFu, tot, m);

    if (k == 0)
        out[b] = tot + __ldg(w0);
}

extern "C" void kernel_launch(void* const* d_in, const int* in_sizes, int n_in,
                              void* d_out, int out_size)
{
    const float* dense  = (const float*)d_in[0];
    const int*   sparse = (const int*)  d_in[1];
    const float* w0     = (const float*)d_in[2];
    const float* w      = (const float*)d_in[3];
    const float* V      = (const float*)d_in[4];
    float*       out    = (float*)d_out;

    const int total  = FM_BATCH * FM_K;            // 65536 threads
    const int blocks = total / CTA_THREADS;        // 512 CTAs
    fm_layer_kernel<<<blocks, CTA_THREADS>>>(dense, sparse, w0, w, V, out);
}